// round 12
// baseline (speedup 1.0000x reference)
#include <cuda_runtime.h>

// Retrace: B=2048, T=512, D=16 (fp32). Single persistent kernel:
//   Phase 1: segmented affine scan — each (chain, segment) thread computes
//            carry_out = A*x + B and loss_seg(x) = sdd - 2x*sAd + x^2*sAA.
//   Grid barrier (2048 blocks co-resident @ 14 blocks/SM, regs<=36).
//   Phase 2: first 256 blocks chain segments from L2, reduce, finalize.
//
// Inputs (metadata order):
//   0: Q [B,T,D]  1: expected_target_Q [B,T,D]  2: target_Q [B,T,D]
//   3: rewards [B,T,D]  4: target_policy_probs [B,T,D]  5: behaviour_policy_probs [B,T]
// Output: scalar fp32 = mean((Q[:, :-1] - q_ret)^2)

#define T_DIM 512
#define D_DIM 16
#define GAMMA 0.99f
#define BLOCK 128
#define SEG 8
#define SEGLEN 64                       // 511 = 8*64 - 1 (last segment: 63 steps)
#define NCHAINS (2048 * 16)             // 32768
#define NBLK ((NCHAINS * SEG) / BLOCK)  // 2048 blocks; 14/SM * 148 = 2072 >= 2048
#define NBLK2 (NCHAINS / BLOCK)         // 256 combine blocks
#define GROUP 3

__device__ float g_sAA[SEG * NCHAINS];
__device__ float g_sAd[SEG * NCHAINS];
__device__ float g_sdd[SEG * NCHAINS];
__device__ float g_A  [SEG * NCHAINS];
__device__ float g_B  [SEG * NCHAINS];
__device__ float g_x0 [NCHAINS];        // TQ[:, -1] stashed by phase 1
__device__ float g_partials[NBLK2];
// Monotonic counters: never reset -> safe across CUDA-graph replays.
__device__ unsigned int g_arrive;
__device__ unsigned int g_ticket;

__global__ __launch_bounds__(BLOCK, 14)  // regs <= 36 -> 14 blocks/SM co-resident
void retrace_fused(const float* __restrict__ Q,
                   const float* __restrict__ E,
                   const float* __restrict__ TQ,
                   const float* __restrict__ R,
                   const float* __restrict__ TPP,
                   const float* __restrict__ BPP,
                   float* __restrict__ out,
                   double inv_count)
{
    // ======================= Phase 1: segment summaries =======================
    {
        const int tid = blockIdx.x * BLOCK + threadIdx.x;
        const int cid = tid & (NCHAINS - 1);     // chain id (d fastest -> coalesced)
        const int s   = tid >> 15;               // segment id, 0..7
        const int b   = cid >> 4;
        const int d   = cid & 15;

        const int lo = s * SEGLEN;
        const int hi = (s == SEG - 1) ? (T_DIM - 2) : (lo + SEGLEN - 1);
        const int n  = hi - lo + 1;              // 64, or 63 for s=7 (63 = 3*21)

        // Shared 32-bit running offsets (array bases stay in uniform regs):
        //   o  indexes R/Q at t       (elements)
        //   o + D_DIM indexes E/TQ/TPP at t+1
        //   ob indexes BPP at t+1
        int o  = b * (T_DIM * D_DIM) + d + hi * D_DIM;
        int ob = b * T_DIM + (hi + 1);

        if (s == SEG - 1)
            g_x0[cid] = TQ[o + D_DIM];           // TQ[:, -1]

        float A = 1.0f, Bv = 0.0f;
        float sAA = 0.0f, sAd = 0.0f, sdd = 0.0f;

        int i = 0;
        for (; i + GROUP <= n; i += GROUP) {
            float r[GROUP], qv[GROUP], e[GROUP], tq[GROUP], tp[GROUP], bp[GROUP];
            #pragma unroll
            for (int k = 0; k < GROUP; ++k) {    // immediate-offset LDGs
                r[k]  = R  [o - k * D_DIM];
                qv[k] = Q  [o - k * D_DIM];
                e[k]  = E  [o + D_DIM - k * D_DIM];
                tq[k] = TQ [o + D_DIM - k * D_DIM];
                tp[k] = TPP[o + D_DIM - k * D_DIM];
                bp[k] = BPP[ob - k];
            }
            #pragma unroll
            for (int k = 0; k < GROUP; ++k) {
                float c  = __expf(fminf(tp[k] - bp[k], 0.0f));
                float m  = GAMMA * c;
                float t1 = fmaf(GAMMA, e[k], r[k]);      // r + g*e
                Bv = fmaf(m, Bv - tq[k], t1);            // B' = m*(B - tq) + t1
                A  = m * A;                              // A' = m*A
                float dv = qv[k] - Bv;                   // df = dv - A'*x
                sdd = fmaf(dv, dv, sdd);
                sAd = fmaf(A, dv, sAd);
                sAA = fmaf(A, A, sAA);
            }
            o  -= GROUP * D_DIM;
            ob -= GROUP;
        }
        for (; i < n; ++i) {                             // remainder (s != 7: 1 step)
            float c  = __expf(fminf(TPP[o + D_DIM] - BPP[ob], 0.0f));
            float m  = GAMMA * c;
            float t1 = fmaf(GAMMA, E[o + D_DIM], R[o]);
            Bv = fmaf(m, Bv - TQ[o + D_DIM], t1);
            A  = m * A;
            float dv = Q[o] - Bv;
            sdd = fmaf(dv, dv, sdd);
            sAd = fmaf(A, dv, sAd);
            sAA = fmaf(A, A, sAA);
            o  -= D_DIM;
            ob -= 1;
        }

        const int idx = s * NCHAINS + cid;
        g_sAA[idx] = sAA;
        g_sAd[idx] = sAd;
        g_sdd[idx] = sdd;
        g_A[idx]   = A;
        g_B[idx]   = Bv;
    }

    // ===================== Grid barrier (monotonic counter) ===================
    __threadfence();                             // publish phase-1 writes
    __shared__ unsigned int s_target;
    __syncthreads();                             // all block threads done above
    if (threadIdx.x == 0) {
        unsigned int t = atomicAdd(&g_arrive, 1u);
        s_target = (t / NBLK + 1u) * NBLK;       // end-count for THIS launch
    }
    __syncthreads();

    if (blockIdx.x >= NBLK2)                     // non-combine blocks: arrive & exit
        return;                                  // (frees slots -> no deadlock risk)

    if (threadIdx.x == 0) {
        while (*(volatile unsigned int*)&g_arrive < s_target) { }
    }
    __syncthreads();
    __threadfence();                             // acquire phase-1 writes

    // ================= Phase 2: chain segments, reduce, finalize ==============
    const int cid = blockIdx.x * BLOCK + threadIdx.x;

    float x = g_x0[cid];
    float loss = 0.0f;

    // Process segments 7..4 then 3..0; loads for each half front-batched
    // (chunked to stay under the 36-reg cap; all L2-resident anyway).
    #pragma unroll
    for (int half = 1; half >= 0; --half) {
        const int sbase = half * 4;
        float aa[4], ad[4], dd[4], Av[4], Bs[4];
        #pragma unroll
        for (int j = 0; j < 4; ++j) {
            const int idx = (sbase + j) * NCHAINS + cid;
            aa[j] = g_sAA[idx];
            ad[j] = g_sAd[idx];
            dd[j] = g_sdd[idx];
            Av[j] = g_A[idx];
            Bs[j] = g_B[idx];
        }
        #pragma unroll
        for (int j = 3; j >= 0; --j) {           // global segment sbase+j, descending
            loss += fmaf(x, fmaf(x, aa[j], -2.0f * ad[j]), dd[j]);
            x = fmaf(Av[j], x, Bs[j]);
        }
    }

    // Deterministic block reduction.
    #pragma unroll
    for (int off = 16; off > 0; off >>= 1)
        loss += __shfl_xor_sync(0xFFFFFFFFu, loss, off);

    __shared__ float s_warp[BLOCK / 32];
    const int lane = threadIdx.x & 31;
    const int wid  = threadIdx.x >> 5;
    if (lane == 0) s_warp[wid] = loss;
    __syncthreads();

    __shared__ bool s_last;
    if (threadIdx.x == 0) {
        g_partials[blockIdx.x] = s_warp[0] + s_warp[1] + s_warp[2] + s_warp[3];
        __threadfence();
        unsigned int t = atomicAdd(&g_ticket, 1u);
        s_last = ((t % NBLK2) == NBLK2 - 1);     // monotonic across replays
    }
    __syncthreads();

    if (s_last) {
        __shared__ double s_d[BLOCK];
        double v = 0.0;
        for (int i = threadIdx.x; i < NBLK2; i += BLOCK)
            v += (double)g_partials[i];
        s_d[threadIdx.x] = v;
        __syncthreads();
        for (int stride = BLOCK >> 1; stride > 0; stride >>= 1) {
            if (threadIdx.x < stride) s_d[threadIdx.x] += s_d[threadIdx.x + stride];
            __syncthreads();
        }
        if (threadIdx.x == 0)
            out[0] = (float)(s_d[0] * inv_count);
    }
}

extern "C" void kernel_launch(void* const* d_in, const int* in_sizes, int n_in,
                              void* d_out, int out_size)
{
    const float* Q   = (const float*)d_in[0];
    const float* E   = (const float*)d_in[1];
    const float* TQ  = (const float*)d_in[2];
    const float* R   = (const float*)d_in[3];
    const float* TPP = (const float*)d_in[4];
    const float* BPP = (const float*)d_in[5];

    const int B = in_sizes[5] / T_DIM;           // 2048
    const double inv_count =
        1.0 / ((double)B * (double)(T_DIM - 1) * (double)D_DIM);

    retrace_fused<<<NBLK, BLOCK>>>(Q, E, TQ, R, TPP, BPP,
                                   (float*)d_out, inv_count);
}

// round 13
// speedup vs baseline: 1.1696x; 1.1696x over previous
#include <cuda_runtime.h>

// Retrace: B=2048, T=512, D=16 (fp32). Single persistent kernel.
// Phase 1: warp-cooperative SMEM-staged segmented affine scan.
//   Each warp owns 32 chains (2 b-rows x 16 d) over one 128-step segment.
//   Per 8-step chunk it loads 5 arrays as 10 dense LDG.128 (512B/warp-request,
//   sequential over t), stores to padded SMEM, and threads consume scalars
//   via conflict-free LDS. Next chunk's LDGs are issued before computing the
//   current chunk (register prefetch) to overlap DRAM latency.
//   Segment summary: carry_out = A*x + B, loss_seg(x) = sdd - 2x*sAd + x^2*sAA.
// Grid barrier (1024 blocks co-resident: >=7 blocks/SM by regs+smem).
// Phase 2: first 256 blocks chain segments from L2, reduce, finalize.
//
// Inputs (metadata order):
//   0: Q [B,T,D]  1: expected_target_Q [B,T,D]  2: target_Q [B,T,D]
//   3: rewards [B,T,D]  4: target_policy_probs [B,T,D]  5: behaviour_policy_probs [B,T]
// Output: scalar fp32 = mean((Q[:, :-1] - q_ret)^2)

#define T_DIM 512
#define D_DIM 16
#define GAMMA 0.99f
#define BLOCK 128
#define SEG 4
#define SEGLEN 128                      // 511 = 4*128 - 1 (segment 3: 127 steps)
#define CH 8                            // steps per chunk
#define NCHUNK (SEGLEN / CH)            // 16
#define NCHAINS (2048 * 16)             // 32768
#define NBLK ((NCHAINS * SEG) / BLOCK)  // 1024 blocks, single co-resident wave
#define NBLK2 (NCHAINS / BLOCK)         // 256 combine blocks

// SMEM layout per warp (floats): 5 arrays x [2b][8t][16d] with b-stride padded
// to 144 (=128+16) for conflict-free LDS, then 16 floats of BPP slab.
#define ARR_STRIDE 288                  // 2 * 144
#define BPP_BASE   1440                 // 5 * 288
#define WARP_SMEM  1472                 // 16B-aligned per-warp stride

__device__ float g_sAA[SEG * NCHAINS];
__device__ float g_sAd[SEG * NCHAINS];
__device__ float g_sdd[SEG * NCHAINS];
__device__ float g_A  [SEG * NCHAINS];
__device__ float g_B  [SEG * NCHAINS];
__device__ float g_x0 [NCHAINS];        // TQ[:, -1] stashed by phase 1
__device__ float g_partials[NBLK2];
// Monotonic counters: never reset -> safe across CUDA-graph replays.
__device__ unsigned int g_arrive;
__device__ unsigned int g_ticket;

__global__ __launch_bounds__(BLOCK, 7)   // regs <= 73; smem 23.5KB -> 7 blocks/SM
void retrace_fused(const float* __restrict__ Q,
                   const float* __restrict__ E,
                   const float* __restrict__ TQ,
                   const float* __restrict__ R,
                   const float* __restrict__ TPP,
                   const float* __restrict__ BPP,
                   float* __restrict__ out,
                   double inv_count)
{
    __shared__ float sm[4][WARP_SMEM];

    const int w    = threadIdx.x >> 5;
    const int lane = threadIdx.x & 31;
    float* S = sm[w];

    // ======================= Phase 1: segment summaries =======================
    {
        const int wid_g = blockIdx.x * 4 + w;          // global warp id
        const int cid0  = (wid_g * 32) & (NCHAINS - 1);
        const int s     = (wid_g * 32) >> 15;          // segment 0..3
        const int cid   = cid0 + lane;
        const int bl    = lane >> 4;                   // b within warp (0/1)
        const int d     = lane & 15;
        const int b0    = cid0 >> 4;                   // warp covers b0, b0+1

        const int hi = (s == SEG - 1) ? (T_DIM - 2) : (s * SEGLEN + SEGLEN - 1);
        const int n  = (s == SEG - 1) ? (SEGLEN - 1) : SEGLEN;

        if (s == SEG - 1)
            g_x0[cid] = TQ[(b0 + bl) * (T_DIM * D_DIM) + (T_DIM - 1) * D_DIM + d];

        float A = 1.0f, Bv = 0.0f;
        float sAA = 0.0f, sAd = 0.0f, sdd = 0.0f;

        float4 v[10];
        float  vb = 0.0f;

        // Chunk load: R/Q slab rows [tc-7, tc]; E/TQ/TPP + BPP rows [tc-6, tc+1].
#define LOADCHUNK(tc)                                                          \
        {                                                                      \
            const int orq = ((tc) - 7) * D_DIM + lane * 4;                     \
            const int oe  = ((tc) - 6) * D_DIM + lane * 4;                     \
            const int g0  =  b0      * (T_DIM * D_DIM);                        \
            const int g1  = (b0 + 1) * (T_DIM * D_DIM);                        \
            v[0] = *(const float4*)(R   + g0 + orq);                           \
            v[1] = *(const float4*)(R   + g1 + orq);                           \
            v[2] = *(const float4*)(Q   + g0 + orq);                           \
            v[3] = *(const float4*)(Q   + g1 + orq);                           \
            v[4] = *(const float4*)(E   + g0 + oe);                            \
            v[5] = *(const float4*)(E   + g1 + oe);                            \
            v[6] = *(const float4*)(TQ  + g0 + oe);                            \
            v[7] = *(const float4*)(TQ  + g1 + oe);                            \
            v[8] = *(const float4*)(TPP + g0 + oe);                            \
            v[9] = *(const float4*)(TPP + g1 + oe);                            \
            if (lane < 16)                                                     \
                vb = BPP[(b0 + (lane >> 3)) * T_DIM + ((tc) - 6) + (lane & 7)];\
        }

        LOADCHUNK(hi);                               // prefetch chunk 0

        for (int c = 0; c < NCHUNK; ++c) {
            // Stage chunk c into SMEM.
            #pragma unroll
            for (int a = 0; a < 5; ++a) {
                *(float4*)(S + a * ARR_STRIDE +       lane * 4) = v[a * 2 + 0];
                *(float4*)(S + a * ARR_STRIDE + 144 + lane * 4) = v[a * 2 + 1];
            }
            if (lane < 16) S[BPP_BASE + lane] = vb;  // [b][trel] == lane
            __syncwarp();

            // Prefetch chunk c+1 (in flight during compute below).
            if (c + 1 < NCHUNK) {
                const int tcn = hi - CH * (c + 1);
                LOADCHUNK(tcn);
            }

            // Compute chunk c from SMEM (steps descend: trel = 7-k).
            const int steps = (n - CH * c < CH) ? (n - CH * c) : CH;
            const int lbase = bl * 144 + d;
            #pragma unroll
            for (int k = 0; k < CH; ++k) {
                if (k >= steps) break;
                const int off = lbase + (7 - k) * D_DIM;
                float r  = S[0 * ARR_STRIDE + off];
                float qv = S[1 * ARR_STRIDE + off];
                float e  = S[2 * ARR_STRIDE + off];
                float tq = S[3 * ARR_STRIDE + off];
                float tp = S[4 * ARR_STRIDE + off];
                float bp = S[BPP_BASE + bl * CH + (7 - k)];

                float cc = __expf(fminf(tp - bp, 0.0f));
                float m  = GAMMA * cc;
                float t1 = fmaf(GAMMA, e, r);        // r + g*e
                Bv = fmaf(m, Bv - tq, t1);           // B' = m*(B - tq) + t1
                A  = m * A;                          // A' = m*A
                float dv = qv - Bv;                  // df = dv - A'*x
                sdd = fmaf(dv, dv, sdd);
                sAd = fmaf(A, dv, sAd);
                sAA = fmaf(A, A, sAA);
            }
            __syncwarp();                            // readers done before next STS
        }
#undef LOADCHUNK

        const int idx = s * NCHAINS + cid;
        g_sAA[idx] = sAA;
        g_sAd[idx] = sAd;
        g_sdd[idx] = sdd;
        g_A[idx]   = A;
        g_B[idx]   = Bv;
    }

    // ===================== Grid barrier (monotonic counter) ===================
    __threadfence();                                 // publish phase-1 writes
    __shared__ unsigned int s_target;
    __syncthreads();
    if (threadIdx.x == 0) {
        unsigned int t = atomicAdd(&g_arrive, 1u);
        s_target = (t / NBLK + 1u) * NBLK;           // end-count for THIS launch
    }
    __syncthreads();

    if (blockIdx.x >= NBLK2)                         // non-combine blocks exit
        return;                                      // (frees slots -> no deadlock)

    if (threadIdx.x == 0) {
        while (*(volatile unsigned int*)&g_arrive < s_target) { }
    }
    __syncthreads();
    __threadfence();                                 // acquire phase-1 writes

    // ================= Phase 2: chain segments, reduce, finalize ==============
    const int cid = blockIdx.x * BLOCK + threadIdx.x;

    float aa[SEG], ad[SEG], dd[SEG], Av[SEG], Bs[SEG];
    #pragma unroll
    for (int s = 0; s < SEG; ++s) {
        const int idx = s * NCHAINS + cid;
        aa[s] = g_sAA[idx];
        ad[s] = g_sAd[idx];
        dd[s] = g_sdd[idx];
        Av[s] = g_A[idx];
        Bs[s] = g_B[idx];
    }
    float x = g_x0[cid];

    float loss = 0.0f;
    #pragma unroll
    for (int s = SEG - 1; s >= 0; --s) {             // latest times first
        loss += fmaf(x, fmaf(x, aa[s], -2.0f * ad[s]), dd[s]);
        x = fmaf(Av[s], x, Bs[s]);
    }

    // Deterministic block reduction.
    #pragma unroll
    for (int off = 16; off > 0; off >>= 1)
        loss += __shfl_xor_sync(0xFFFFFFFFu, loss, off);

    __shared__ float s_warp[BLOCK / 32];
    if ((threadIdx.x & 31) == 0) s_warp[threadIdx.x >> 5] = loss;
    __syncthreads();

    __shared__ bool s_last;
    if (threadIdx.x == 0) {
        g_partials[blockIdx.x] = s_warp[0] + s_warp[1] + s_warp[2] + s_warp[3];
        __threadfence();
        unsigned int t = atomicAdd(&g_ticket, 1u);
        s_last = ((t % NBLK2) == NBLK2 - 1);         // monotonic across replays
    }
    __syncthreads();

    if (s_last) {
        __shared__ double s_d[BLOCK];
        double v = 0.0;
        for (int i = threadIdx.x; i < NBLK2; i += BLOCK)
            v += (double)g_partials[i];
        s_d[threadIdx.x] = v;
        __syncthreads();
        for (int stride = BLOCK >> 1; stride > 0; stride >>= 1) {
            if (threadIdx.x < stride) s_d[threadIdx.x] += s_d[threadIdx.x + stride];
            __syncthreads();
        }
        if (threadIdx.x == 0)
            out[0] = (float)(s_d[0] * inv_count);
    }
}

extern "C" void kernel_launch(void* const* d_in, const int* in_sizes, int n_in,
                              void* d_out, int out_size)
{
    const float* Q   = (const float*)d_in[0];
    const float* E   = (const float*)d_in[1];
    const float* TQ  = (const float*)d_in[2];
    const float* R   = (const float*)d_in[3];
    const float* TPP = (const float*)d_in[4];
    const float* BPP = (const float*)d_in[5];

    const int B = in_sizes[5] / T_DIM;               // 2048
    const double inv_count =
        1.0 / ((double)B * (double)(T_DIM - 1) * (double)D_DIM);

    retrace_fused<<<NBLK, BLOCK>>>(Q, E, TQ, R, TPP, BPP,
                                   (float*)d_out, inv_count);
}

// round 14
// speedup vs baseline: 1.1955x; 1.0221x over previous
#include <cuda_runtime.h>

// Retrace: B=2048, T=512, D=16 (fp32). Single persistent kernel.
// Phase 1: warp-cooperative cp.async-staged segmented affine scan.
//   Each warp owns 32 chains (2 b-rows x 16 d) over one 128-step segment.
//   Per 4-step chunk: 5 arrays arrive as dense 512B warp requests via
//   cp.async.cg (L1-bypass, no register buffer), BPP via cp.async.ca 4B.
//   TWO SMEM stages -> loads run ~2 chunk-cycles ahead of compute.
//   Segment summary: carry_out = A*x + B, loss_seg(x) = sdd - 2x*sAd + x^2*sAA.
// Grid barrier (1024 blocks co-resident: regs<=64, smem 26KB -> >=7 blocks/SM).
// Phase 2: first 256 blocks chain segments from L2, reduce, finalize.
//
// Inputs (metadata order):
//   0: Q [B,T,D]  1: expected_target_Q [B,T,D]  2: target_Q [B,T,D]
//   3: rewards [B,T,D]  4: target_policy_probs [B,T,D]  5: behaviour_policy_probs [B,T]
// Output: scalar fp32 = mean((Q[:, :-1] - q_ret)^2)

#define T_DIM 512
#define D_DIM 16
#define GAMMA 0.99f
#define BLOCK 128
#define SEG 4
#define SEGLEN 128                      // 511 = 4*128 - 1 (segment 3: 127 steps)
#define CH 4                            // steps per chunk
#define NCHUNK (SEGLEN / CH)            // 32
#define NCHAINS (2048 * 16)             // 32768
#define NBLK ((NCHAINS * SEG) / BLOCK)  // 1024 blocks, single co-resident wave
#define NBLK2 (NCHAINS / BLOCK)         // 256 combine blocks

// Per-warp stage layout (float words):
//   array a at a*ASTR, b-row bl at +bl*BSTR (padded: 80 = 64+16 -> conflict-free),
//   t-rel tr at +tr*16 + d.  BPP slab (2b x 4t) at BPPOFF.
#define BSTR   80
#define ASTR   160                      // 2 * BSTR
#define BPPOFF 800                      // 5 * ASTR
#define SSZ    816                      // stage size (16B-aligned: 816*4 = 3264)
#define NSTAGE 2

__device__ float g_sAA[SEG * NCHAINS];
__device__ float g_sAd[SEG * NCHAINS];
__device__ float g_sdd[SEG * NCHAINS];
__device__ float g_A  [SEG * NCHAINS];
__device__ float g_B  [SEG * NCHAINS];
__device__ float g_x0 [NCHAINS];        // TQ[:, -1] stashed by phase 1
__device__ float g_partials[NBLK2];
// Monotonic counters: never reset -> safe across CUDA-graph replays.
__device__ unsigned int g_arrive;
__device__ unsigned int g_ticket;

#define CPA16(dst, src) \
    asm volatile("cp.async.cg.shared.global [%0], [%1], 16;\n" \
                 :: "r"(dst), "l"(src))
#define CPA4(dst, src) \
    asm volatile("cp.async.ca.shared.global [%0], [%1], 4;\n" \
                 :: "r"(dst), "l"(src))
#define CPA_COMMIT()  asm volatile("cp.async.commit_group;\n")
#define CPA_WAIT1()   asm volatile("cp.async.wait_group 1;\n")
#define CPA_WAIT0()   asm volatile("cp.async.wait_group 0;\n")

__global__ __launch_bounds__(BLOCK, 7)   // regs <= 64; smem ~26KB -> 7+ blocks/SM
void retrace_fused(const float* __restrict__ Q,
                   const float* __restrict__ E,
                   const float* __restrict__ TQ,
                   const float* __restrict__ R,
                   const float* __restrict__ TPP,
                   const float* __restrict__ BPP,
                   float* __restrict__ out,
                   double inv_count)
{
    __shared__ float sm[4][NSTAGE * SSZ];

    const int w    = threadIdx.x >> 5;
    const int lane = threadIdx.x & 31;
    float* Swarp = sm[w];

    // ======================= Phase 1: segment summaries =======================
    {
        const int wid_g = blockIdx.x * 4 + w;          // global warp id
        const int cid0  = (wid_g * 32) & (NCHAINS - 1);
        const int s     = (wid_g * 32) >> 15;          // segment 0..3
        const int cid   = cid0 + lane;
        const int bl    = lane >> 4;                   // b within warp (0/1)
        const int d     = lane & 15;
        const int b0    = cid0 >> 4;                   // warp covers b0, b0+1

        const int hi = (s == SEG - 1) ? (T_DIM - 2) : (s * SEGLEN + SEGLEN - 1);
        const int n  = (s == SEG - 1) ? (SEGLEN - 1) : SEGLEN;

        if (s == SEG - 1)
            g_x0[cid] = TQ[(b0 + bl) * (T_DIM * D_DIM) + (T_DIM - 1) * D_DIM + d];

        const unsigned sbase =
            (unsigned)__cvta_generic_to_shared(Swarp);
        const int half = lane >> 4;                    // loader role: b-row
        const int l16  = lane & 15;
        const int grow = (b0 + half) * (T_DIM * D_DIM);
        const int brow = (b0 + half) * T_DIM;

        // Issue all cp.async for chunk at top-t `tc` into stage `stg`.
#define ISSUE(tc, stg)                                                         \
        {                                                                      \
            const int orq = ((tc) - 3) * D_DIM + l16 * 4;   /* R/Q rows   */   \
            const int oe  = ((tc) - 2) * D_DIM + l16 * 4;   /* E/TQ/TPP   */   \
            const unsigned dstS = sbase + (unsigned)((stg) * SSZ * 4);         \
            const unsigned dst0 = dstS + (unsigned)((half * BSTR + l16 * 4) * 4);\
            CPA16(dst0 + 0u * (ASTR * 4), R   + grow + orq);                   \
            CPA16(dst0 + 1u * (ASTR * 4), Q   + grow + orq);                   \
            CPA16(dst0 + 2u * (ASTR * 4), E   + grow + oe);                    \
            CPA16(dst0 + 3u * (ASTR * 4), TQ  + grow + oe);                    \
            CPA16(dst0 + 4u * (ASTR * 4), TPP + grow + oe);                    \
            if (l16 < 4)                                                       \
                CPA4(dstS + (unsigned)((BPPOFF + half * 4 + l16) * 4),         \
                     BPP + brow + ((tc) - 2) + l16);                           \
            CPA_COMMIT();                                                      \
        }

        float A = 1.0f, Bv = 0.0f;
        float sAA = 0.0f, sAd = 0.0f, sdd = 0.0f;

        ISSUE(hi,          0);                        // chunk 0 -> stage 0
        ISSUE(hi - CH,     1);                        // chunk 1 -> stage 1

        for (int c = 0; c < NCHUNK; ++c) {
            if (c < NCHUNK - 1) { CPA_WAIT1(); } else { CPA_WAIT0(); }
            __syncwarp();                             // cross-lane visibility

            // Compute chunk c from its stage (steps descend: tr = 3-k).
            const float* St = Swarp + (c & 1) * SSZ;
            const int steps = (n - CH * c < CH) ? (n - CH * c) : CH;
            #pragma unroll
            for (int k = 0; k < CH; ++k) {
                if (k >= steps) break;
                const int off = bl * BSTR + (3 - k) * D_DIM + d;
                float r  = St[0 * ASTR + off];
                float qv = St[1 * ASTR + off];
                float e  = St[2 * ASTR + off];
                float tq = St[3 * ASTR + off];
                float tp = St[4 * ASTR + off];
                float bp = St[BPPOFF + bl * 4 + (3 - k)];

                float cc = __expf(fminf(tp - bp, 0.0f));
                float m  = GAMMA * cc;
                float t1 = fmaf(GAMMA, e, r);         // r + g*e
                Bv = fmaf(m, Bv - tq, t1);            // B' = m*(B - tq) + t1
                A  = m * A;                           // A' = m*A
                float dv = qv - Bv;                   // df = dv - A'*x
                sdd = fmaf(dv, dv, sdd);
                sAd = fmaf(A, dv, sAd);
                sAA = fmaf(A, A, sAA);
            }
            __syncwarp();                             // reads done before overwrite

            if (c + 2 < NCHUNK)
                ISSUE(hi - CH * (c + 2), c & 1);      // refill the stage just freed
        }
#undef ISSUE

        const int idx = s * NCHAINS + cid;
        g_sAA[idx] = sAA;
        g_sAd[idx] = sAd;
        g_sdd[idx] = sdd;
        g_A[idx]   = A;
        g_B[idx]   = Bv;
    }

    // ===================== Grid barrier (monotonic counter) ===================
    __threadfence();                                  // publish phase-1 writes
    __shared__ unsigned int s_target;
    __syncthreads();
    if (threadIdx.x == 0) {
        unsigned int t = atomicAdd(&g_arrive, 1u);
        s_target = (t / NBLK + 1u) * NBLK;            // end-count for THIS launch
    }
    __syncthreads();

    if (blockIdx.x >= NBLK2)                          // non-combine blocks exit
        return;                                       // (frees slots -> no deadlock)

    if (threadIdx.x == 0) {
        while (*(volatile unsigned int*)&g_arrive < s_target) { }
    }
    __syncthreads();
    __threadfence();                                  // acquire phase-1 writes

    // ================= Phase 2: chain segments, reduce, finalize ==============
    const int cid = blockIdx.x * BLOCK + threadIdx.x;

    float aa[SEG], ad[SEG], dd[SEG], Av[SEG], Bs[SEG];
    #pragma unroll
    for (int s = 0; s < SEG; ++s) {
        const int idx = s * NCHAINS + cid;
        aa[s] = g_sAA[idx];
        ad[s] = g_sAd[idx];
        dd[s] = g_sdd[idx];
        Av[s] = g_A[idx];
        Bs[s] = g_B[idx];
    }
    float x = g_x0[cid];

    float loss = 0.0f;
    #pragma unroll
    for (int s = SEG - 1; s >= 0; --s) {              // latest times first
        loss += fmaf(x, fmaf(x, aa[s], -2.0f * ad[s]), dd[s]);
        x = fmaf(Av[s], x, Bs[s]);
    }

    // Deterministic block reduction.
    #pragma unroll
    for (int off = 16; off > 0; off >>= 1)
        loss += __shfl_xor_sync(0xFFFFFFFFu, loss, off);

    __shared__ float s_warp[BLOCK / 32];
    if ((threadIdx.x & 31) == 0) s_warp[threadIdx.x >> 5] = loss;
    __syncthreads();

    __shared__ bool s_last;
    if (threadIdx.x == 0) {
        g_partials[blockIdx.x] = s_warp[0] + s_warp[1] + s_warp[2] + s_warp[3];
        __threadfence();
        unsigned int t = atomicAdd(&g_ticket, 1u);
        s_last = ((t % NBLK2) == NBLK2 - 1);          // monotonic across replays
    }
    __syncthreads();

    if (s_last) {
        __shared__ double s_d[BLOCK];
        double v = 0.0;
        for (int i = threadIdx.x; i < NBLK2; i += BLOCK)
            v += (double)g_partials[i];
        s_d[threadIdx.x] = v;
        __syncthreads();
        for (int stride = BLOCK >> 1; stride > 0; stride >>= 1) {
            if (threadIdx.x < stride) s_d[threadIdx.x] += s_d[threadIdx.x + stride];
            __syncthreads();
        }
        if (threadIdx.x == 0)
            out[0] = (float)(s_d[0] * inv_count);
    }
}

extern "C" void kernel_launch(void* const* d_in, const int* in_sizes, int n_in,
                              void* d_out, int out_size)
{
    const float* Q   = (const float*)d_in[0];
    const float* E   = (const float*)d_in[1];
    const float* TQ  = (const float*)d_in[2];
    const float* R   = (const float*)d_in[3];
    const float* TPP = (const float*)d_in[4];
    const float* BPP = (const float*)d_in[5];

    const int B = in_sizes[5] / T_DIM;                // 2048
    const double inv_count =
        1.0 / ((double)B * (double)(T_DIM - 1) * (double)D_DIM);

    retrace_fused<<<NBLK, BLOCK>>>(Q, E, TQ, R, TPP, BPP,
                                   (float*)d_out, inv_count);
}